// round 2
// baseline (speedup 1.0000x reference)
#include <cuda_runtime.h>
#include <math.h>

#define HID 256
#define HSZ 512
#define NH 8
#define HD 64
#define NTOK 8
#define BB 8
#define EPSV 1e-6f

typedef unsigned long long ull;

// scratch (allocation-free: device globals)
__device__ __align__(16) float g_qh[BB * HSZ];          // [b][hd]
__device__ __align__(16) float g_wq2[BB * HID * NH];    // [b][ch][head]  (scale+rms_w folded)
__device__ __align__(16) float g_wv2[HID * HSZ];        // [ch][head*64+d] (rms_w folded)

__device__ __forceinline__ void fma2(ull& d, ull a, ull b) {
    asm("fma.rn.f32x2 %0, %1, %2, %0;" : "+l"(d) : "l"(a), "l"(b));
}
__device__ __forceinline__ ull pk2(float x, float y) {
    ull r; asm("mov.b64 %0, {%1, %2};" : "=l"(r) : "f"(x), "f"(y)); return r;
}
__device__ __forceinline__ float2 upk(ull v) {
    float2 f; asm("mov.b64 {%0, %1}, %2;" : "=f"(f.x), "=f"(f.y) : "l"(v)); return f;
}

// ---------------- precompute: qh = (silu(emb[q]@w1+b1))@w2 + b2 ----------------
__global__ void k_qh(const int* __restrict__ q, const float* __restrict__ emb,
                     const float* __restrict__ w1, const float* __restrict__ b1,
                     const float* __restrict__ w2, const float* __restrict__ b2) {
    int b = blockIdx.x;
    int t = threadIdx.x;  // 256
    __shared__ float qe[HID];
    __shared__ float t1[HSZ];
    int qi = q[b];
    qe[t] = emb[(size_t)qi * HID + t];
    __syncthreads();
    for (int rep = 0; rep < 2; rep++) {
        int i = t + rep * 256;
        float acc = b1[i];
#pragma unroll 4
        for (int ch = 0; ch < HID; ch++) acc += qe[ch] * w1[ch * HSZ + i];
        t1[i] = acc / (1.0f + expf(-acc));  // silu
    }
    __syncthreads();
    for (int rep = 0; rep < 2; rep++) {
        int i = t + rep * 256;
        float acc = b2[i];
#pragma unroll 4
        for (int k = 0; k < HSZ; k++) acc += t1[k] * w2[k * HSZ + i];
        g_qh[b * HSZ + i] = acc;
    }
}

// -------- precompute effective query weights: wq2[b][ch][head] --------
// k column layout in w_kv: col = head*128 + d  (v: head*128 + 64 + d)
__global__ void k_wq2(const float* __restrict__ w_kv, const float* __restrict__ rms_w) {
    int b = blockIdx.x;
    int ch = threadIdx.x;  // 256
    __shared__ float qh_s[HSZ];
    qh_s[ch] = g_qh[b * HSZ + ch];
    qh_s[ch + 256] = g_qh[b * HSZ + ch + 256];
    __syncthreads();
    float rw = 0.125f * rms_w[ch];  // attn_scale = 64^-0.5
    const float* row = w_kv + (size_t)ch * (2 * HSZ);
#pragma unroll
    for (int hh = 0; hh < NH; hh++) {
        float s = 0.f;
#pragma unroll
        for (int d = 0; d < HD; d++) s += row[hh * 128 + d] * qh_s[hh * HD + d];
        g_wq2[(b * HID + ch) * NH + hh] = rw * s;
    }
}

// -------- precompute V weights with rms_w folded: wv2[ch][head*64+d] --------
__global__ void k_wv2(const float* __restrict__ w_kv, const float* __restrict__ rms_w) {
    int idx = blockIdx.x * 256 + threadIdx.x;  // grid 512 -> 131072
    int ch = idx >> 9;
    int hd = idx & 511;
    int head = hd >> 6, d = hd & 63;
    g_wv2[idx] = rms_w[ch] * w_kv[(size_t)ch * 1024 + head * 128 + 64 + d];
}

// ---------------- main fused kernel: one block per (b, h) row of 32 pixels ----------------
// smem layout (floats):
//   region X [0, 16416): phase1/2: wq2_s[2048] @0, ds_s[32*73] @2048, rinv_s[8*33] @4384
//                        phase4:   h_s[32*513] @0
//   region Y [16416, 22560): phase3: c_s[8*8*32]=2048 @16416, wv_s[8*512]=4096 @18464
//                            phase4: wout_s[16*256]=4096 @16416
#define SMEM_FLOATS (16416 + 6144)
#define CH_TILE 8
#define HD_TILE 16

__global__ void __launch_bounds__(256, 2)
k_main(const float* __restrict__ c, float* __restrict__ out,
       const float* __restrict__ w_out, const float* __restrict__ b_out) {
    extern __shared__ float sm[];
    float* wq2_s = sm;                 // 2048
    float* ds_s = sm + 2048;           // 2336
    float* rinv_s = sm + 4384;         // 264
    float* h_s = sm;                   // 16416 (aliases phase1/2 bufs)
    float* c_s = sm + 16416;           // 2048
    float* wv_s = sm + 18464;          // 4096
    float* wout_s = sm + 16416;        // 4096 (aliases c_s/wv_s)

    const int tid = threadIdx.x;
    const int w = tid & 31;
    const int g = tid >> 5;  // phase1: n, phase2/3: head, phase4: cog
    const int bb = blockIdx.x >> 5;
    const int h = blockIdx.x & 31;

    // stage wq2[b] -> smem ([ch][head], 2048 floats)
    {
        const float* src = g_wq2 + bb * 2048;
        for (int i = tid; i < 2048; i += 256) wq2_s[i] = src[i];
    }
    __syncthreads();

    // ---- phase 1: thread (n=g, w): ssq + dots for all 8 heads over 256 ch
    {
        const float* cbase = c + ((size_t)(bb * NTOK + g)) * HID * 1024 + h * 32 + w;
        ull dp0 = 0, dp1 = 0, dp2 = 0, dp3 = 0;
        float ssq = 0.f;
#pragma unroll 4
        for (int ch = 0; ch < HID; ch++) {
            float cv = cbase[(size_t)ch * 1024];
            ssq += cv * cv;
            ull cc = pk2(cv, cv);
            const ull* wr = (const ull*)(wq2_s + ch * 8);
            fma2(dp0, cc, wr[0]);
            fma2(dp1, cc, wr[1]);
            fma2(dp2, cc, wr[2]);
            fma2(dp3, cc, wr[3]);
        }
        float rinv = rsqrtf(ssq * (1.0f / HID) + EPSV);
        float* dst = ds_s + w * 73 + g * 9;  // [w][n][head]
        float2 v;
        v = upk(dp0); dst[0] = v.x * rinv; dst[1] = v.y * rinv;
        v = upk(dp1); dst[2] = v.x * rinv; dst[3] = v.y * rinv;
        v = upk(dp2); dst[4] = v.x * rinv; dst[5] = v.y * rinv;
        v = upk(dp3); dst[6] = v.x * rinv; dst[7] = v.y * rinv;
        rinv_s[g * 33 + w] = rinv;
    }
    __syncthreads();

    // ---- phase 2: thread (head=g, w): softmax over n; aw[n] = attn[n]*rinv[n] in regs
    float aw[8];
    {
        const float* dsrc = ds_s + w * 73 + g;  // stride 9 over n
        float d[8], m = -1e30f;
#pragma unroll
        for (int n = 0; n < 8; n++) { d[n] = dsrc[n * 9]; m = fmaxf(m, d[n]); }
        float s = 0.f;
#pragma unroll
        for (int n = 0; n < 8; n++) { d[n] = expf(d[n] - m); s += d[n]; }
        float inv = 1.0f / s;
#pragma unroll
        for (int n = 0; n < 8; n++) aw[n] = d[n] * inv * rinv_s[n * 33 + w];
    }
    __syncthreads();  // ds_s / rinv_s dead beyond this point

    // ---- phase 3: h[head*64+d] accumulation over ch tiles (packed f32x2)
    ull hacc[32];
#pragma unroll
    for (int j = 0; j < 32; j++) hacc[j] = 0ull;
    const float* cblk = c + (size_t)bb * NTOK * HID * 1024 + h * 32;
    const int head = g;
    for (int ct = 0; ct < HID; ct += CH_TILE) {
        // stage c tile: c_s[n][chi][w]
#pragma unroll
        for (int r = 0; r < 8; r++) {
            int e = tid + r * 256;
            int ww_ = e & 31;
            int chi = (e >> 5) & 7;
            int n = e >> 8;
            c_s[e] = cblk[((size_t)(n * HID + ct + chi)) * 1024 + ww_];
        }
        // stage wv tile: wv_s[chi][512]
        {
            const float4* src = (const float4*)(g_wv2 + ct * HSZ);
            float4* dstv = (float4*)wv_s;
#pragma unroll
            for (int r = 0; r < 4; r++) dstv[tid + r * 256] = src[tid + r * 256];
        }
        __syncthreads();
#pragma unroll
        for (int chi = 0; chi < CH_TILE; chi++) {
            float cb = 0.f;
            const float* cc = c_s + (chi << 5) + w;
#pragma unroll
            for (int n = 0; n < 8; n++) cb += aw[n] * cc[n << 8];
            ull cb2 = pk2(cb, cb);
            const ulonglong2* wr = (const ulonglong2*)(wv_s + chi * HSZ + head * HD);
#pragma unroll
            for (int j = 0; j < 16; j++) {
                ulonglong2 p = wr[j];
                fma2(hacc[2 * j], cb2, p.x);
                fma2(hacc[2 * j + 1], cb2, p.y);
            }
        }
        __syncthreads();
    }
    // spill h to smem: h_s[w][head*64+d], row stride 513 (conflict-free)
    {
        float* hdst = h_s + w * 513 + head * HD;
#pragma unroll
        for (int j = 0; j < 32; j++) {
            float2 v = upk(hacc[j]);
            hdst[2 * j] = v.x;
            hdst[2 * j + 1] = v.y;
        }
    }
    __syncthreads();

    // ---- phase 4: thread (cog=g, w): out[co=g*32..+31] = b_out + h @ Wout
    ull oacc[16];
    {
        const ulonglong2* bsrc = (const ulonglong2*)(b_out + g * 32);
#pragma unroll
        for (int j = 0; j < 8; j++) {
            ulonglong2 p = bsrc[j];
            oacc[2 * j] = p.x;
            oacc[2 * j + 1] = p.y;
        }
    }
    for (int ht = 0; ht < HSZ; ht += HD_TILE) {
        {
            const float4* src = (const float4*)(w_out + (size_t)ht * HID);
            float4* dstv = (float4*)wout_s;
#pragma unroll
            for (int r = 0; r < 4; r++) dstv[tid + r * 256] = src[tid + r * 256];
        }
        __syncthreads();
#pragma unroll
        for (int hi = 0; hi < HD_TILE; hi++) {
            float hv = h_s[w * 513 + ht + hi];
            ull h2 = pk2(hv, hv);
            const ulonglong2* wr = (const ulonglong2*)(wout_s + hi * HID + g * 32);
#pragma unroll
            for (int j = 0; j < 8; j++) {
                ulonglong2 p = wr[j];
                fma2(oacc[2 * j], h2, p.x);
                fma2(oacc[2 * j + 1], h2, p.y);
            }
        }
        __syncthreads();
    }
    // write out[b][co][h][w]
    {
        float* obase = out + (((size_t)bb * HID + g * 32) * 32 + h) * 32 + w;
#pragma unroll
        for (int j = 0; j < 16; j++) {
            float2 v = upk(oacc[j]);
            obase[(size_t)(2 * j) * 1024] = v.x;
            obase[(size_t)(2 * j + 1) * 1024] = v.y;
        }
    }
}

extern "C" void kernel_launch(void* const* d_in, const int* in_sizes, int n_in,
                              void* d_out, int out_size) {
    const int* q = (const int*)d_in[0];
    const float* c = (const float*)d_in[1];
    const float* rms_w = (const float*)d_in[2];
    const float* emb = (const float*)d_in[3];
    const float* w1 = (const float*)d_in[4];
    const float* b1 = (const float*)d_in[5];
    const float* w2 = (const float*)d_in[6];
    const float* b2 = (const float*)d_in[7];
    const float* w_kv = (const float*)d_in[8];
    const float* w_out = (const float*)d_in[9];
    const float* b_out = (const float*)d_in[10];
    float* out = (float*)d_out;

    k_qh<<<8, 256>>>(q, emb, w1, b1, w2, b2);
    k_wq2<<<8, 256>>>(w_kv, rms_w);
    k_wv2<<<512, 256>>>(w_kv, rms_w);

    int smem_bytes = SMEM_FLOATS * (int)sizeof(float);  // 90240 B
    cudaFuncSetAttribute(k_main, cudaFuncAttributeMaxDynamicSharedMemorySize, smem_bytes);
    k_main<<<256, 256, smem_bytes>>>(c, out, w_out, b_out);
}

// round 4
// speedup vs baseline: 1.5879x; 1.5879x over previous
#include <cuda_runtime.h>
#include <math.h>

#define HID 256
#define HSZ 512
#define NH 8
#define HD 64
#define NTOK 8
#define BB 8
#define EPSV 1e-6f

typedef unsigned long long ull;

// scratch (allocation-free: device globals)
__device__ __align__(16) float g_t1[BB * HSZ];
__device__ __align__(16) float g_qh[BB * HSZ];          // [b][hd]
__device__ __align__(16) float g_wq2[BB * HID * NH];    // [b][ch][head]  (scale+rms_w folded)
__device__ __align__(16) float g_wv2[HID * HSZ];        // [ch][head*64+d] (rms_w folded)

__device__ __forceinline__ void fma2(ull& d, ull a, ull b) {
    asm("fma.rn.f32x2 %0, %1, %2, %0;" : "+l"(d) : "l"(a), "l"(b));
}
__device__ __forceinline__ ull pk2(float x, float y) {
    ull r; asm("mov.b64 %0, {%1, %2};" : "=l"(r) : "f"(x), "f"(y)); return r;
}
__device__ __forceinline__ float2 upk(ull v) {
    float2 f; asm("mov.b64 {%0, %1}, %2;" : "=f"(f.x), "=f"(f.y) : "l"(v)); return f;
}

// ---- precompute 1a: t1 = silu(emb[q]@w1 + b1)   grid(8,4) x 128 ----
__global__ void k_qh1(const int* __restrict__ q, const float* __restrict__ emb,
                      const float* __restrict__ w1, const float* __restrict__ b1) {
    int b = blockIdx.x;
    int t = threadIdx.x;
    int i = blockIdx.y * 128 + t;
    __shared__ float qe[HID];
    int qi = q[b];
    qe[t] = emb[(size_t)qi * HID + t];
    qe[t + 128] = emb[(size_t)qi * HID + t + 128];
    __syncthreads();
    float acc = b1[i];
#pragma unroll 8
    for (int ch = 0; ch < HID; ch++) acc += qe[ch] * w1[ch * HSZ + i];
    g_t1[b * HSZ + i] = acc / (1.0f + expf(-acc));
}

// ---- precompute 1b: qh = t1@w2 + b2   grid(8,4) x 128 ----
__global__ void k_qh2(const float* __restrict__ w2, const float* __restrict__ b2) {
    int b = blockIdx.x;
    int t = threadIdx.x;
    int i = blockIdx.y * 128 + t;
    __shared__ float t1s[HSZ];
#pragma unroll
    for (int r = 0; r < 4; r++) t1s[t + r * 128] = g_t1[b * HSZ + t + r * 128];
    __syncthreads();
    float acc = b2[i];
#pragma unroll 8
    for (int k = 0; k < HSZ; k++) acc += t1s[k] * w2[k * HSZ + i];
    g_qh[b * HSZ + i] = acc;
}

// ---- precompute 2: wq2[b][ch][head] = 0.125*rms_w[ch]*sum_d w_kv[ch][head*128+d]*qh[b][head*64+d]
// one warp per ch; lane handles d=lane and d=lane+32; coalesced LDG + shfl reduce.
__global__ void k_wq2(const float* __restrict__ w_kv, const float* __restrict__ rms_w) {
    int warp = (blockIdx.x * blockDim.x + threadIdx.x) >> 5;  // 0..255 = ch
    int lane = threadIdx.x & 31;
    int ch = warp;
    float rw = 0.125f * rms_w[ch];
    const float* row = w_kv + (size_t)ch * 1024;
#pragma unroll
    for (int hh = 0; hh < NH; hh++) {
        float wv0 = row[hh * 128 + lane];
        float wv1 = row[hh * 128 + lane + 32];
#pragma unroll
        for (int b = 0; b < BB; b++) {
            float p = wv0 * g_qh[b * HSZ + hh * HD + lane]
                    + wv1 * g_qh[b * HSZ + hh * HD + lane + 32];
#pragma unroll
            for (int o = 16; o > 0; o >>= 1) p += __shfl_xor_sync(0xffffffffu, p, o);
            if (lane == 0) g_wq2[(b * HID + ch) * NH + hh] = rw * p;
        }
    }
}

// ---- precompute 3: wv2[ch][head*64+d] = rms_w[ch]*w_kv[ch][head*128+64+d] ----
__global__ void k_wv2(const float* __restrict__ w_kv, const float* __restrict__ rms_w) {
    int idx = blockIdx.x * 256 + threadIdx.x;  // 131072
    int ch = idx >> 9;
    int hd = idx & 511;
    int head = hd >> 6, d = hd & 63;
    g_wv2[idx] = rms_w[ch] * w_kv[(size_t)ch * 1024 + head * 128 + 64 + d];
}

// ---------------- main fused kernel: one block per (b, h) row of 32 pixels ----------------
// smem (floats):
//  region X [0,16416): p1/2: wq2_s[2048]@0, ds_s[2336]@2048, rinv_s[264]@4384 ; p3spill/p4: h_s[32*513]@0
//  region Y [16416,22560): p3: cbar_s[2048]@16416, wv_s[4096]@18464 ; p4: wout_s[4096]@16416
#define SMEM_FLOATS 22560
#define CH_TILE 8
#define HD_TILE 16

__global__ void __launch_bounds__(256, 2)
k_main(const float* __restrict__ c, float* __restrict__ out,
       const float* __restrict__ w_out, const float* __restrict__ b_out) {
    extern __shared__ float sm[];
    float* wq2_s = sm;
    float* ds_s = sm + 2048;
    float* rinv_s = sm + 4384;
    float* h_s = sm;            // 16416 (aliases phase1/2 bufs)
    float* cbar_s = sm + 16416; // 2048
    float* wv_s = sm + 18464;   // 4096
    float* wout_s = sm + 16416; // 4096 (aliases cbar/wv)

    const int tid = threadIdx.x;
    const int lane = tid & 31;
    const int g = tid >> 5;  // phase1: n, phase2/3: head, phase4: cog
    const int bb = blockIdx.x >> 5;
    const int h = blockIdx.x & 31;

    // stage wq2[b] -> smem ([ch][head], 2048 floats)
    {
        const float4* src = (const float4*)(g_wq2 + bb * 2048);
        float4* dst = (float4*)wq2_s;
#pragma unroll
        for (int r = 0; r < 2; r++) dst[tid + r * 256] = src[tid + r * 256];
    }
    __syncthreads();

    // ---- phase 1: thread (n=g, w=lane): ssq + dots for all 8 heads over 256 ch
    {
        const float* cbase = c + ((size_t)(bb * NTOK + g)) * HID * 1024 + h * 32 + lane;
        ull dp0 = 0, dp1 = 0, dp2 = 0, dp3 = 0;
        float ssq = 0.f;
#pragma unroll 4
        for (int ch = 0; ch < HID; ch++) {
            float cv = cbase[(size_t)ch * 1024];
            ssq += cv * cv;
            ull cc = pk2(cv, cv);
            const ulonglong2* wr = (const ulonglong2*)(wq2_s + ch * 8);
            ulonglong2 q0 = wr[0], q1 = wr[1];
            fma2(dp0, cc, q0.x);
            fma2(dp1, cc, q0.y);
            fma2(dp2, cc, q1.x);
            fma2(dp3, cc, q1.y);
        }
        float rinv = rsqrtf(ssq * (1.0f / HID) + EPSV);
        float* dst = ds_s + lane * 73 + g * 9;  // [w][n][head]
        float2 v;
        v = upk(dp0); dst[0] = v.x * rinv; dst[1] = v.y * rinv;
        v = upk(dp1); dst[2] = v.x * rinv; dst[3] = v.y * rinv;
        v = upk(dp2); dst[4] = v.x * rinv; dst[5] = v.y * rinv;
        v = upk(dp3); dst[6] = v.x * rinv; dst[7] = v.y * rinv;
        rinv_s[g * 33 + lane] = rinv;
    }
    __syncthreads();

    // ---- phase 2: thread (head=g, w=lane): softmax over n; aw[n]=attn[n]*rinv[n]
    float aw[8];
    {
        const float* dsrc = ds_s + lane * 73 + g;
        float d[8], m = -1e30f;
#pragma unroll
        for (int n = 0; n < 8; n++) { d[n] = dsrc[n * 9]; m = fmaxf(m, d[n]); }
        float s = 0.f;
#pragma unroll
        for (int n = 0; n < 8; n++) { d[n] = expf(d[n] - m); s += d[n]; }
        float inv = 1.0f / s;
#pragma unroll
        for (int n = 0; n < 8; n++) aw[n] = d[n] * inv * rinv_s[n * 33 + lane];
    }
    __syncthreads();  // ds_s/rinv_s dead

    // ---- phase 3: h = cbar @ wv2 per head, register-tiled GEMM
    const int pq = lane & 7;   // pixel quad (pix = pq*4..+3)
    const int hdg = lane >> 3; // 16-col group within head
    ull hacc[32];
#pragma unroll
    for (int j = 0; j < 32; j++) hacc[j] = 0ull;
    const float* cb_b = c + (size_t)bb * NTOK * HID * 1024 + h * 32 + lane;

    for (int ct = 0; ct < HID; ct += CH_TILE) {
        // stage wv tile [chi][512]
        {
            const float4* src = (const float4*)(g_wv2 + ct * HSZ);
            float4* dstv = (float4*)wv_s;
#pragma unroll
            for (int r = 0; r < 4; r++) dstv[tid + r * 256] = src[tid + r * 256];
        }
        // cbar: thread (head=g, w=lane): cbar[g][chi][w] = sum_n aw[n]*c[n][ct+chi][h][w]
#pragma unroll 2
        for (int chi = 0; chi < CH_TILE; chi++) {
            float cbv = 0.f;
#pragma unroll
            for (int n = 0; n < 8; n++)
                cbv += aw[n] * cb_b[((size_t)(n * HID + ct + chi)) * 1024];
            cbar_s[(g * 8 + chi) * 32 + lane] = cbv;
        }
        __syncthreads();
        // GEMM: thread (head=g, pq, hdg): 4 pix x 16 cols
#pragma unroll
        for (int chi = 0; chi < CH_TILE; chi++) {
            float4 cq = *(const float4*)(cbar_s + (g * 8 + chi) * 32 + pq * 4);
            const ulonglong2* wr = (const ulonglong2*)(wv_s + chi * HSZ + g * HD + hdg * 16);
            ulonglong2 w0 = wr[0], w1v = wr[1], w2v = wr[2], w3v = wr[3];
            {
                ull cp = pk2(cq.x, cq.x);
                fma2(hacc[0], cp, w0.x); fma2(hacc[1], cp, w0.y);
                fma2(hacc[2], cp, w1v.x); fma2(hacc[3], cp, w1v.y);
                fma2(hacc[4], cp, w2v.x); fma2(hacc[5], cp, w2v.y);
                fma2(hacc[6], cp, w3v.x); fma2(hacc[7], cp, w3v.y);
            }
            {
                ull cp = pk2(cq.y, cq.y);
                fma2(hacc[8], cp, w0.x); fma2(hacc[9], cp, w0.y);
                fma2(hacc[10], cp, w1v.x); fma2(hacc[11], cp, w1v.y);
                fma2(hacc[12], cp, w2v.x); fma2(hacc[13], cp, w2v.y);
                fma2(hacc[14], cp, w3v.x); fma2(hacc[15], cp, w3v.y);
            }
            {
                ull cp = pk2(cq.z, cq.z);
                fma2(hacc[16], cp, w0.x); fma2(hacc[17], cp, w0.y);
                fma2(hacc[18], cp, w1v.x); fma2(hacc[19], cp, w1v.y);
                fma2(hacc[20], cp, w2v.x); fma2(hacc[21], cp, w2v.y);
                fma2(hacc[22], cp, w3v.x); fma2(hacc[23], cp, w3v.y);
            }
            {
                ull cp = pk2(cq.w, cq.w);
                fma2(hacc[24], cp, w0.x); fma2(hacc[25], cp, w0.y);
                fma2(hacc[26], cp, w1v.x); fma2(hacc[27], cp, w1v.y);
                fma2(hacc[28], cp, w2v.x); fma2(hacc[29], cp, w2v.y);
                fma2(hacc[30], cp, w3v.x); fma2(hacc[31], cp, w3v.y);
            }
        }
        __syncthreads();
    }
    // spill h to h_s[pix*513 + hd]
    {
        int hd0 = g * HD + hdg * 16;
#pragma unroll
        for (int p = 0; p < 4; p++) {
            float* hdst = h_s + (pq * 4 + p) * 513 + hd0;
#pragma unroll
            for (int j = 0; j < 8; j++) {
                float2 v = upk(hacc[p * 8 + j]);
                hdst[2 * j] = v.x;
                hdst[2 * j + 1] = v.y;
            }
        }
    }
    __syncthreads();

    // ---- phase 4: thread (cog=g, pq, csub): out[4 pix][8 co] = b_out + h @ Wout
    const int csub = lane >> 3;
    const int cobase = g * 32 + csub * 8;
    ull oacc[16];  // oacc[p*4+j] = co pair (2j,2j+1), pixel pq*4+p
    {
        const ulonglong2* bsrc = (const ulonglong2*)(b_out + cobase);
        ulonglong2 b0 = bsrc[0], b1v = bsrc[1];
#pragma unroll
        for (int p = 0; p < 4; p++) {
            oacc[p * 4 + 0] = b0.x; oacc[p * 4 + 1] = b0.y;
            oacc[p * 4 + 2] = b1v.x; oacc[p * 4 + 3] = b1v.y;
        }
    }
    for (int ht = 0; ht < HSZ; ht += HD_TILE) {
        {
            const float4* src = (const float4*)(w_out + (size_t)ht * HID);
            float4* dstv = (float4*)wout_s;
#pragma unroll
            for (int r = 0; r < 4; r++) dstv[tid + r * 256] = src[tid + r * 256];
        }
        __syncthreads();
#pragma unroll 4
        for (int hi = 0; hi < HD_TILE; hi++) {
            float hv0 = h_s[(pq * 4 + 0) * 513 + ht + hi];
            float hv1 = h_s[(pq * 4 + 1) * 513 + ht + hi];
            float hv2 = h_s[(pq * 4 + 2) * 513 + ht + hi];
            float hv3 = h_s[(pq * 4 + 3) * 513 + ht + hi];
            const ulonglong2* wr = (const ulonglong2*)(wout_s + hi * HID + cobase);
            ulonglong2 wo0 = wr[0], wo1 = wr[1];
            ull cp;
            cp = pk2(hv0, hv0);
            fma2(oacc[0], cp, wo0.x); fma2(oacc[1], cp, wo0.y);
            fma2(oacc[2], cp, wo1.x); fma2(oacc[3], cp, wo1.y);
            cp = pk2(hv1, hv1);
            fma2(oacc[4], cp, wo0.x); fma2(oacc[5], cp, wo0.y);
            fma2(oacc[6], cp, wo1.x); fma2(oacc[7], cp, wo1.y);
            cp = pk2(hv2, hv2);
            fma2(oacc[8], cp, wo0.x); fma2(oacc[9], cp, wo0.y);
            fma2(oacc[10], cp, wo1.x); fma2(oacc[11], cp, wo1.y);
            cp = pk2(hv3, hv3);
            fma2(oacc[12], cp, wo0.x); fma2(oacc[13], cp, wo0.y);
            fma2(oacc[14], cp, wo1.x); fma2(oacc[15], cp, wo1.y);
        }
        __syncthreads();
    }
    // store: for each of 8 co, STG.128 over pixel quad
    {
        float* obase = out + (((size_t)bb * HID + cobase) * 32 + h) * 32 + pq * 4;
#pragma unroll
        for (int j = 0; j < 4; j++) {
            float2 v0 = upk(oacc[0 * 4 + j]);
            float2 v1 = upk(oacc[1 * 4 + j]);
            float2 v2 = upk(oacc[2 * 4 + j]);
            float2 v3 = upk(oacc[3 * 4 + j]);
            float4 lo = make_float4(v0.x, v1.x, v2.x, v3.x);  // co = cobase+2j
            float4 hi4 = make_float4(v0.y, v1.y, v2.y, v3.y); // co = cobase+2j+1
            *(float4*)(obase + (size_t)(2 * j) * 1024) = lo;
            *(float4*)(obase + (size_t)(2 * j + 1) * 1024) = hi4;
        }
    }
}

extern "C" void kernel_launch(void* const* d_in, const int* in_sizes, int n_in,
                              void* d_out, int out_size) {
    const int* q = (const int*)d_in[0];
    const float* c = (const float*)d_in[1];
    const float* rms_w = (const float*)d_in[2];
    const float* emb = (const float*)d_in[3];
    const float* w1 = (const float*)d_in[4];
    const float* b1 = (const float*)d_in[5];
    const float* w2 = (const float*)d_in[6];
    const float* b2 = (const float*)d_in[7];
    const float* w_kv = (const float*)d_in[8];
    const float* w_out = (const float*)d_in[9];
    const float* b_out = (const float*)d_in[10];
    float* out = (float*)d_out;

    k_qh1<<<dim3(8, 4), 128>>>(q, emb, w1, b1);
    k_qh2<<<dim3(8, 4), 128>>>(w2, b2);
    k_wq2<<<32, 256>>>(w_kv, rms_w);
    k_wv2<<<512, 256>>>(w_kv, rms_w);

    int smem_bytes = SMEM_FLOATS * (int)sizeof(float);  // 90240 B
    cudaFuncSetAttribute(k_main, cudaFuncAttributeMaxDynamicSharedMemorySize, smem_bytes);
    k_main<<<256, 256, smem_bytes>>>(c, out, w_out, b_out);
}

// round 5
// speedup vs baseline: 1.6029x; 1.0094x over previous
#include <cuda_runtime.h>
#include <math.h>

#define HID 256
#define HSZ 512
#define NH 8
#define HD 64
#define NTOK 8
#define BB 8
#define EPSV 1e-6f
#define HSTRIDE 36

typedef unsigned long long ull;

__device__ __align__(16) float g_qh[BB * HSZ];          // [b][hd]
__device__ __align__(16) float g_wq2[BB * HID * NH];    // [b][ch][head] (scale+rms folded)
__device__ __align__(16) float g_wv2[HID * HSZ];        // [ch][head*64+d] (rms folded)

__device__ __forceinline__ void fma2(ull& d, ull a, ull b) {
    asm("fma.rn.f32x2 %0, %1, %2, %0;" : "+l"(d) : "l"(a), "l"(b));
}
__device__ __forceinline__ ull pk2(float x, float y) {
    ull r; asm("mov.b64 %0, {%1, %2};" : "=l"(r) : "f"(x), "f"(y)); return r;
}
__device__ __forceinline__ float2 upk(ull v) {
    float2 f; asm("mov.b64 {%0, %1}, %2;" : "=f"(f.x), "=f"(f.y) : "l"(v)); return f;
}

// ---- k_pre: blocks 0-7: qh MLP (per batch); blocks 8-519: wv2 scaling ----
__global__ void k_pre(const int* __restrict__ q, const float* __restrict__ emb,
                      const float* __restrict__ w1, const float* __restrict__ b1,
                      const float* __restrict__ w2, const float* __restrict__ b2,
                      const float* __restrict__ w_kv, const float* __restrict__ rms_w) {
    __shared__ float qe[HID];
    __shared__ float t1s[HSZ];
    int t = threadIdx.x;
    if (blockIdx.x >= 8) {
        // wv2[ch][head*64+d] = rms_w[ch] * w_kv[ch][head*128+64+d]
        int idx = (blockIdx.x - 8) * 256 + t;  // 131072 total
        int ch = idx >> 9;
        int hd = idx & 511;
        int head = hd >> 6, d = hd & 63;
        g_wv2[idx] = rms_w[ch] * w_kv[(size_t)ch * 1024 + head * 128 + 64 + d];
        return;
    }
    int b = blockIdx.x;
    int qi = q[b];
    qe[t] = emb[(size_t)qi * HID + t];
    __syncthreads();
#pragma unroll
    for (int rep = 0; rep < 2; rep++) {
        int i = t + rep * 256;
        float acc = b1[i];
#pragma unroll 8
        for (int ch = 0; ch < HID; ch++) acc += qe[ch] * w1[ch * HSZ + i];
        t1s[i] = acc / (1.0f + expf(-acc));  // silu
    }
    __syncthreads();
#pragma unroll
    for (int rep = 0; rep < 2; rep++) {
        int i = t + rep * 256;
        float acc = b2[i];
#pragma unroll 8
        for (int k = 0; k < HSZ; k++) acc += t1s[k] * w2[k * HSZ + i];
        g_qh[b * HSZ + i] = acc;
    }
}

// ---- k_wq2: warp per ch; wq2[b][ch][head] = 0.125*rms_w[ch]*sum_d Wk*qh ----
__global__ void k_wq2(const float* __restrict__ w_kv, const float* __restrict__ rms_w) {
    int ch = (blockIdx.x * blockDim.x + threadIdx.x) >> 5;  // 0..255
    int lane = threadIdx.x & 31;
    float rw = 0.125f * rms_w[ch];
    const float* row = w_kv + (size_t)ch * 1024;
#pragma unroll
    for (int hh = 0; hh < NH; hh++) {
        float wv0 = row[hh * 128 + lane];
        float wv1 = row[hh * 128 + lane + 32];
#pragma unroll
        for (int b = 0; b < BB; b++) {
            float p = wv0 * g_qh[b * HSZ + hh * HD + lane]
                    + wv1 * g_qh[b * HSZ + hh * HD + lane + 32];
#pragma unroll
            for (int o = 16; o > 0; o >>= 1) p += __shfl_xor_sync(0xffffffffu, p, o);
            if (lane == 0) g_wq2[(b * HID + ch) * NH + hh] = rw * p;
        }
    }
}

// ---------------- main fused kernel: one block per (b, h) row of 32 pixels ----------------
// smem (floats):
//  region X [0,18432): p1/2: wq2_s[2048]@0, ds_s[2336]@2048, rinv_s[264]@4384
//                      p3spill/p4: h_s[512*36]@0  (transposed: [hd][pix])
//  region Y [18432,26624): p3: c_s[2048]@18432, cbar_s[2048]@20480, wv_s[4096]@22528
//                          p4: wout_s[4096]@18432
#define SMEM_FLOATS 26624
#define CH_TILE 8
#define HD_TILE 16

__global__ void __launch_bounds__(256, 2)
k_main(const float* __restrict__ c, float* __restrict__ out,
       const float* __restrict__ w_out, const float* __restrict__ b_out) {
    extern __shared__ float sm[];
    float* wq2_s = sm;
    float* ds_s = sm + 2048;
    float* rinv_s = sm + 4384;
    float* h_s = sm;             // 18432 (aliases phase1/2 bufs)
    float* c_s = sm + 18432;     // 2048
    float* cbar_s = sm + 20480;  // 2048
    float* wv_s = sm + 22528;    // 4096
    float* wout_s = sm + 18432;  // 4096 (aliases c_s/cbar_s)

    const int tid = threadIdx.x;
    const int lane = tid & 31;
    const int g = tid >> 5;  // p1: n, p2/3: head, p4: cog
    const int bb = blockIdx.x >> 5;
    const int h = blockIdx.x & 31;

    // stage wq2[b] -> smem ([ch][head], 2048 floats)
    {
        const float4* src = (const float4*)(g_wq2 + bb * 2048);
        float4* dst = (float4*)wq2_s;
#pragma unroll
        for (int r = 0; r < 2; r++) dst[tid + r * 256] = src[tid + r * 256];
    }
    __syncthreads();

    // ---- phase 1: thread (n=g, w=lane): ssq + 8 head dots over 256 ch
    {
        const float* cbase = c + ((size_t)(bb * NTOK + g)) * HID * 1024 + h * 32 + lane;
        ull dp0 = 0, dp1 = 0, dp2 = 0, dp3 = 0;
        float ssq = 0.f;
#pragma unroll 4
        for (int ch = 0; ch < HID; ch++) {
            float cv = cbase[(size_t)ch * 1024];
            ssq += cv * cv;
            ull cc = pk2(cv, cv);
            const ulonglong2* wr = (const ulonglong2*)(wq2_s + ch * 8);
            ulonglong2 q0 = wr[0], q1 = wr[1];
            fma2(dp0, cc, q0.x);
            fma2(dp1, cc, q0.y);
            fma2(dp2, cc, q1.x);
            fma2(dp3, cc, q1.y);
        }
        float rinv = rsqrtf(ssq * (1.0f / HID) + EPSV);
        float* dst = ds_s + lane * 73 + g * 9;  // [w][n][head]
        float2 v;
        v = upk(dp0); dst[0] = v.x * rinv; dst[1] = v.y * rinv;
        v = upk(dp1); dst[2] = v.x * rinv; dst[3] = v.y * rinv;
        v = upk(dp2); dst[4] = v.x * rinv; dst[5] = v.y * rinv;
        v = upk(dp3); dst[6] = v.x * rinv; dst[7] = v.y * rinv;
        rinv_s[g * 33 + lane] = rinv;
    }
    __syncthreads();

    // ---- phase 2: thread (head=g, w=lane): softmax; aw[n]=attn[n]*rinv[n]
    float aw[8];
    {
        const float* dsrc = ds_s + lane * 73 + g;
        float d[8], m = -1e30f;
#pragma unroll
        for (int n = 0; n < 8; n++) { d[n] = dsrc[n * 9]; m = fmaxf(m, d[n]); }
        float s = 0.f;
#pragma unroll
        for (int n = 0; n < 8; n++) { d[n] = expf(d[n] - m); s += d[n]; }
        float inv = 1.0f / s;
#pragma unroll
        for (int n = 0; n < 8; n++) aw[n] = d[n] * inv * rinv_s[n * 33 + lane];
    }
    __syncthreads();  // ds_s/rinv_s dead

    // ---- phase 3: h = cbar @ wv2 per head (c staged once; register-tiled GEMM)
    const int pq = lane & 7;   // pixel quad
    const int hdg = lane >> 3; // 16-col group within head
    ull hacc[32];
#pragma unroll
    for (int j = 0; j < 32; j++) hacc[j] = 0ull;
    const float* cblk = c + (size_t)bb * NTOK * HID * 1024 + h * 32;

    for (int ct = 0; ct < HID; ct += CH_TILE) {
        // stage wv tile [chi][512]
        {
            const float4* src = (const float4*)(g_wv2 + ct * HSZ);
            float4* dstv = (float4*)wv_s;
#pragma unroll
            for (int r = 0; r < 4; r++) dstv[tid + r * 256] = src[tid + r * 256];
        }
        // stage c tile: c_s[(n*8+chi)*32 + w] — each value LDG'd exactly once
#pragma unroll
        for (int r = 0; r < 8; r++) {
            int e = tid + r * 256;
            int n = e >> 8;
            int chi = (e >> 5) & 7;
            int ww = e & 31;
            c_s[e] = cblk[((size_t)(n * HID + ct + chi)) * 1024 + ww];
        }
        __syncthreads();
        // cbar: thread (head=g, w=lane) from smem
#pragma unroll
        for (int chi = 0; chi < CH_TILE; chi++) {
            float cbv = 0.f;
#pragma unroll
            for (int n = 0; n < 8; n++) cbv += aw[n] * c_s[(n * 8 + chi) * 32 + lane];
            cbar_s[(g * 8 + chi) * 32 + lane] = cbv;
        }
        __syncwarp();  // GEMM reads only own-warp cbar rows
        // GEMM: thread (head=g, pq, hdg): 4 pix x 16 cols
#pragma unroll
        for (int chi = 0; chi < CH_TILE; chi++) {
            float4 cq = *(const float4*)(cbar_s + (g * 8 + chi) * 32 + pq * 4);
            const ulonglong2* wr = (const ulonglong2*)(wv_s + chi * HSZ + g * HD + hdg * 16);
            ulonglong2 w0 = wr[0], w1v = wr[1], w2v = wr[2], w3v = wr[3];
            {
                ull cp = pk2(cq.x, cq.x);
                fma2(hacc[0], cp, w0.x);  fma2(hacc[1], cp, w0.y);
                fma2(hacc[2], cp, w1v.x); fma2(hacc[3], cp, w1v.y);
                fma2(hacc[4], cp, w2v.x); fma2(hacc[5], cp, w2v.y);
                fma2(hacc[6], cp, w3v.x); fma2(hacc[7], cp, w3v.y);
            }
            {
                ull cp = pk2(cq.y, cq.y);
                fma2(hacc[8], cp, w0.x);  fma2(hacc[9], cp, w0.y);
                fma2(hacc[10], cp, w1v.x); fma2(hacc[11], cp, w1v.y);
                fma2(hacc[12], cp, w2v.x); fma2(hacc[13], cp, w2v.y);
                fma2(hacc[14], cp, w3v.x); fma2(hacc[15], cp, w3v.y);
            }
            {
                ull cp = pk2(cq.z, cq.z);
                fma2(hacc[16], cp, w0.x);  fma2(hacc[17], cp, w0.y);
                fma2(hacc[18], cp, w1v.x); fma2(hacc[19], cp, w1v.y);
                fma2(hacc[20], cp, w2v.x); fma2(hacc[21], cp, w2v.y);
                fma2(hacc[22], cp, w3v.x); fma2(hacc[23], cp, w3v.y);
            }
            {
                ull cp = pk2(cq.w, cq.w);
                fma2(hacc[24], cp, w0.x);  fma2(hacc[25], cp, w0.y);
                fma2(hacc[26], cp, w1v.x); fma2(hacc[27], cp, w1v.y);
                fma2(hacc[28], cp, w2v.x); fma2(hacc[29], cp, w2v.y);
                fma2(hacc[30], cp, w3v.x); fma2(hacc[31], cp, w3v.y);
            }
        }
        __syncthreads();
    }
    // spill h TRANSPOSED: h_s[hd*36 + pix]
    {
        int hd0 = g * HD + hdg * 16;
#pragma unroll
        for (int p = 0; p < 4; p++) {
            int pix = pq * 4 + p;
#pragma unroll
            for (int j = 0; j < 8; j++) {
                float2 v = upk(hacc[p * 8 + j]);
                h_s[(hd0 + 2 * j) * HSTRIDE + pix] = v.x;
                h_s[(hd0 + 2 * j + 1) * HSTRIDE + pix] = v.y;
            }
        }
    }
    __syncthreads();

    // ---- phase 4: thread (cog=g, pq, csub): out[4 pix][8 co] = b_out + h @ Wout
    const int csub = lane >> 3;
    const int cobase = g * 32 + csub * 8;
    ull oacc[16];  // oacc[p*4+j] = co pair (2j,2j+1), pixel pq*4+p
    {
        const ulonglong2* bsrc = (const ulonglong2*)(b_out + cobase);
        ulonglong2 b0 = bsrc[0], b1v = bsrc[1];
#pragma unroll
        for (int p = 0; p < 4; p++) {
            oacc[p * 4 + 0] = b0.x;  oacc[p * 4 + 1] = b0.y;
            oacc[p * 4 + 2] = b1v.x; oacc[p * 4 + 3] = b1v.y;
        }
    }
    for (int ht = 0; ht < HSZ; ht += HD_TILE) {
        {
            const float4* src = (const float4*)(w_out + (size_t)ht * HID);
            float4* dstv = (float4*)wout_s;
#pragma unroll
            for (int r = 0; r < 4; r++) dstv[tid + r * 256] = src[tid + r * 256];
        }
        __syncthreads();
#pragma unroll 4
        for (int hi = 0; hi < HD_TILE; hi++) {
            float4 hp = *(const float4*)(h_s + (ht + hi) * HSTRIDE + pq * 4);  // 4 pixels
            const ulonglong2* wr = (const ulonglong2*)(wout_s + hi * HID + cobase);
            ulonglong2 wo0 = wr[0], wo1 = wr[1];
            ull cp;
            cp = pk2(hp.x, hp.x);
            fma2(oacc[0], cp, wo0.x);  fma2(oacc[1], cp, wo0.y);
            fma2(oacc[2], cp, wo1.x);  fma2(oacc[3], cp, wo1.y);
            cp = pk2(hp.y, hp.y);
            fma2(oacc[4], cp, wo0.x);  fma2(oacc[5], cp, wo0.y);
            fma2(oacc[6], cp, wo1.x);  fma2(oacc[7], cp, wo1.y);
            cp = pk2(hp.z, hp.z);
            fma2(oacc[8], cp, wo0.x);  fma2(oacc[9], cp, wo0.y);
            fma2(oacc[10], cp, wo1.x); fma2(oacc[11], cp, wo1.y);
            cp = pk2(hp.w, hp.w);
            fma2(oacc[12], cp, wo0.x); fma2(oacc[13], cp, wo0.y);
            fma2(oacc[14], cp, wo1.x); fma2(oacc[15], cp, wo1.y);
        }
        __syncthreads();
    }
    // store: for each of 8 co, STG.128 over pixel quad
    {
        float* obase = out + (((size_t)bb * HID + cobase) * 32 + h) * 32 + pq * 4;
#pragma unroll
        for (int j = 0; j < 4; j++) {
            float2 v0 = upk(oacc[0 * 4 + j]);
            float2 v1 = upk(oacc[1 * 4 + j]);
            float2 v2 = upk(oacc[2 * 4 + j]);
            float2 v3 = upk(oacc[3 * 4 + j]);
            float4 lo = make_float4(v0.x, v1.x, v2.x, v3.x);   // co = cobase+2j
            float4 hi4 = make_float4(v0.y, v1.y, v2.y, v3.y);  // co = cobase+2j+1
            *(float4*)(obase + (size_t)(2 * j) * 1024) = lo;
            *(float4*)(obase + (size_t)(2 * j + 1) * 1024) = hi4;
        }
    }
}

extern "C" void kernel_launch(void* const* d_in, const int* in_sizes, int n_in,
                              void* d_out, int out_size) {
    const int* q = (const int*)d_in[0];
    const float* c = (const float*)d_in[1];
    const float* rms_w = (const float*)d_in[2];
    const float* emb = (const float*)d_in[3];
    const float* w1 = (const float*)d_in[4];
    const float* b1 = (const float*)d_in[5];
    const float* w2 = (const float*)d_in[6];
    const float* b2 = (const float*)d_in[7];
    const float* w_kv = (const float*)d_in[8];
    const float* w_out = (const float*)d_in[9];
    const float* b_out = (const float*)d_in[10];
    float* out = (float*)d_out;

    k_pre<<<520, 256>>>(q, emb, w1, b1, w2, b2, w_kv, rms_w);
    k_wq2<<<32, 256>>>(w_kv, rms_w);

    int smem_bytes = SMEM_FLOATS * (int)sizeof(float);  // 106496 B
    cudaFuncSetAttribute(k_main, cudaFuncAttributeMaxDynamicSharedMemorySize, smem_bytes);
    k_main<<<256, 256, smem_bytes>>>(c, out, w_out, b_out);
}